// round 1
// baseline (speedup 1.0000x reference)
#include <cuda_runtime.h>

#define BSZ 4096
#define D 128
#define TWO_B 8192
#define COLSPLITS 2
#define TM 128
#define TN 128
#define NTHREADS 256

// Scratch (device-global; no allocations allowed in kernel_launch)
__device__ float g_Z[TWO_B * D];              // normalized z, 4 MB
__device__ float g_pos[BSZ];                  // dot(z_i, z_j)
__device__ float g_partial[COLSPLITS * TWO_B];// per-colsplit rowsums of exp(sim/T)

// exp(2*s) via exp2 polynomial on the FMA pipe (avoid MUFU throughput wall).
// t = s*2*log2(e) in [-2.9, 2.9]; round-to-nearest split, deg-4 Taylor of 2^f,
// |f|<=0.5 -> rel err <= ~5e-5. ~10 fma/alu ops.
__device__ __forceinline__ float fast_exp_2x(float s) {
    float t = s * 2.8853900817779268f;   // 2/ln(2)... = 2*log2(e)
    int   i = __float2int_rn(t);
    float f = t - (float)i;
    float p = 9.6179669e-3f;
    p = fmaf(p, f, 5.5503358e-2f);
    p = fmaf(p, f, 2.4022646e-1f);
    p = fmaf(p, f, 6.9314718e-1f);
    p = fmaf(p, f, 1.0f);
    return __int_as_float((i + 127) << 23) * p;
}

// ---------------------------------------------------------------------------
// Kernel 1: normalize rows of proj_1/proj_2, store z, compute positives.
// One warp per row-pair. D=128 -> 4 floats per lane (one float4).
// ---------------------------------------------------------------------------
__global__ void normalize_kernel(const float* __restrict__ p1,
                                 const float* __restrict__ p2) {
    int warp = (blockIdx.x * blockDim.x + threadIdx.x) >> 5;
    int lane = threadIdx.x & 31;
    if (warp >= BSZ) return;

    float4 a = *(const float4*)&p1[warp * D + lane * 4];
    float4 b = *(const float4*)&p2[warp * D + lane * 4];

    float ss1 = a.x*a.x + a.y*a.y + a.z*a.z + a.w*a.w;
    float ss2 = b.x*b.x + b.y*b.y + b.z*b.z + b.w*b.w;
    #pragma unroll
    for (int o = 16; o > 0; o >>= 1) {
        ss1 += __shfl_xor_sync(0xFFFFFFFFu, ss1, o);
        ss2 += __shfl_xor_sync(0xFFFFFFFFu, ss2, o);
    }
    float r1 = rsqrtf(fmaxf(ss1, 1e-16f));   // matches max(||x||, 1e-8)
    float r2 = rsqrtf(fmaxf(ss2, 1e-16f));

    float4 z1 = make_float4(a.x*r1, a.y*r1, a.z*r1, a.w*r1);
    float4 z2 = make_float4(b.x*r2, b.y*r2, b.z*r2, b.w*r2);
    *(float4*)&g_Z[warp * D + lane * 4]         = z1;
    *(float4*)&g_Z[(warp + BSZ) * D + lane * 4] = z2;

    float d = z1.x*z2.x + z1.y*z2.y + z1.z*z2.z + z1.w*z2.w;
    #pragma unroll
    for (int o = 16; o > 0; o >>= 1)
        d += __shfl_xor_sync(0xFFFFFFFFu, d, o);
    if (lane == 0) g_pos[warp] = d;
}

// ---------------------------------------------------------------------------
// Kernel 2: for each row tile (128 rows) x column split (4096 cols),
// accumulate rowsum of exp(2 * <z_r, z_c>).
// Full K=128 held in smem per tile (A: 64KB, B: 64KB, transposed [k][row]).
// 256 threads, 8x8 microtile with split 4+4 fragments (rows ty*4 & 64+ty*4,
// cols tx*4 & 64+tx*4) for conflict-light LDS.128.
// ---------------------------------------------------------------------------
extern __shared__ float smem_dyn[];

__global__ void __launch_bounds__(NTHREADS, 1) simsum_kernel() {
    float* As = smem_dyn;             // [k][r], 128*128
    float* Bs = smem_dyn + 128 * 128; // [k][c], 128*128

    int tid = threadIdx.x;
    int rowbase = blockIdx.x * TM;
    int colsplit = blockIdx.y;

    // ---- load A tile (transposed) once ----
    #pragma unroll
    for (int it = 0; it < 16; ++it) {
        int idx = it * NTHREADS + tid;      // 0..4095 float4 slots
        int r  = idx & 127;
        int kq = idx >> 7;                  // 0..31
        float4 v = *(const float4*)&g_Z[(rowbase + r) * D + kq * 4];
        As[(kq * 4 + 0) * 128 + r] = v.x;
        As[(kq * 4 + 1) * 128 + r] = v.y;
        As[(kq * 4 + 2) * 128 + r] = v.z;
        As[(kq * 4 + 3) * 128 + r] = v.w;
    }

    int tx = tid & 15, ty = tid >> 4;

    float rowacc[8];
    #pragma unroll
    for (int i = 0; i < 8; ++i) rowacc[i] = 0.0f;

    int colbase0 = colsplit * (TWO_B / COLSPLITS);
    const int ntiles = (TWO_B / COLSPLITS) / TN;

    for (int tile = 0; tile < ntiles; ++tile) {
        int colbase = colbase0 + tile * TN;

        __syncthreads();   // protect Bs from previous tile's readers (and A load first iter)
        #pragma unroll
        for (int it = 0; it < 16; ++it) {
            int idx = it * NTHREADS + tid;
            int c  = idx & 127;
            int kq = idx >> 7;
            float4 v = *(const float4*)&g_Z[(colbase + c) * D + kq * 4];
            Bs[(kq * 4 + 0) * 128 + c] = v.x;
            Bs[(kq * 4 + 1) * 128 + c] = v.y;
            Bs[(kq * 4 + 2) * 128 + c] = v.z;
            Bs[(kq * 4 + 3) * 128 + c] = v.w;
        }
        __syncthreads();

        float acc[8][8];
        #pragma unroll
        for (int i = 0; i < 8; ++i)
            #pragma unroll
            for (int j = 0; j < 8; ++j) acc[i][j] = 0.0f;

        #pragma unroll 8
        for (int k = 0; k < 128; ++k) {
            float4 A0 = *(const float4*)&As[k * 128 + ty * 4];
            float4 A1 = *(const float4*)&As[k * 128 + 64 + ty * 4];
            float4 B0 = *(const float4*)&Bs[k * 128 + tx * 4];
            float4 B1 = *(const float4*)&Bs[k * 128 + 64 + tx * 4];
            float av[8] = {A0.x, A0.y, A0.z, A0.w, A1.x, A1.y, A1.z, A1.w};
            float bv[8] = {B0.x, B0.y, B0.z, B0.w, B1.x, B1.y, B1.z, B1.w};
            #pragma unroll
            for (int i = 0; i < 8; ++i)
                #pragma unroll
                for (int j = 0; j < 8; ++j)
                    acc[i][j] = fmaf(av[i], bv[j], acc[i][j]);
        }

        // epilogue: exp(2*sim) and accumulate per-row
        #pragma unroll
        for (int i = 0; i < 8; ++i) {
            float s = 0.0f;
            #pragma unroll
            for (int j = 0; j < 8; ++j)
                s += fast_exp_2x(acc[i][j]);
            rowacc[i] += s;
        }
    }

    // ---- cross-thread row reduction ----
    __shared__ float rsum[TM];
    __syncthreads();
    if (tid < TM) rsum[tid] = 0.0f;
    __syncthreads();
    #pragma unroll
    for (int i = 0; i < 8; ++i) {
        int row = (i < 4) ? (ty * 4 + i) : (64 + ty * 4 + (i - 4));
        atomicAdd(&rsum[row], rowacc[i]);
    }
    __syncthreads();
    if (tid < TM)
        g_partial[colsplit * TWO_B + rowbase + tid] = rsum[tid];
}

// ---------------------------------------------------------------------------
// Kernel 3: loss = mean_r( log(denom_r) - 2*pos_{r mod B} ),
// denom_r = rowsum_r - exp(2)   (diagonal term; sim_ii = 1 to ~1e-7)
// ---------------------------------------------------------------------------
__global__ void finalize_kernel(float* __restrict__ out) {
    __shared__ float red[256];
    int tid = threadIdx.x;
    float s = 0.0f;
    for (int r = tid; r < TWO_B; r += 256) {
        float denom = g_partial[r] + g_partial[TWO_B + r] - 7.3890560989306495f;
        float pos = g_pos[r & (BSZ - 1)];
        s += __logf(denom) - 2.0f * pos;
    }
    red[tid] = s;
    __syncthreads();
    #pragma unroll
    for (int st = 128; st > 0; st >>= 1) {
        if (tid < st) red[tid] += red[tid + st];
        __syncthreads();
    }
    if (tid == 0) out[0] = red[0] / (float)TWO_B;
}

// ---------------------------------------------------------------------------
extern "C" void kernel_launch(void* const* d_in, const int* in_sizes, int n_in,
                              void* d_out, int out_size) {
    const float* p1 = (const float*)d_in[0];
    const float* p2 = (const float*)d_in[1];
    float* out = (float*)d_out;
    (void)in_sizes; (void)n_in; (void)out_size;

    // 128 KB dynamic smem for the GEMM tile kernel
    cudaFuncSetAttribute(simsum_kernel,
                         cudaFuncAttributeMaxDynamicSharedMemorySize,
                         128 * 1024);

    normalize_kernel<<<BSZ / 8, 256>>>(p1, p2);                 // 8 warps/block
    simsum_kernel<<<dim3(TWO_B / TM, COLSPLITS), NTHREADS, 128 * 1024>>>();
    finalize_kernel<<<1, 256>>>(out);
}

// round 3
// speedup vs baseline: 5.1180x; 5.1180x over previous
#include <cuda_runtime.h>
#include <cuda_bf16.h>
#include <cstdint>

#define BSZ 4096
#define D 128
#define TWO_B 8192
#define COLSPLITS 2
#define TM 128          // rows per CTA
#define TN 128          // cols per tile
#define NTHREADS 256
#define NTILES (TWO_B / COLSPLITS / TN)   // 32

// padded smem row stride: 136 bf16 = 272 B = 17 x 16B -> conflict-free ldmatrix
#define LDS_ELEM 136
#define LDS_BYTES (LDS_ELEM * 2)          // 272
#define TILE_BYTES (128 * LDS_BYTES)      // 34816

#define OFF_A    0
#define OFF_B0   TILE_BYTES
#define OFF_B1   (2 * TILE_BYTES)
#define OFF_RSUM (3 * TILE_BYTES)
#define SMEM_TOTAL (OFF_RSUM + TM * 4)

// ---------------- device scratch ----------------
__device__ __align__(256) __nv_bfloat16 g_Zbf16[TWO_B * D];  // 2 MB
__device__ float g_pos[BSZ];
__device__ float g_partial[COLSPLITS * TWO_B];

static __device__ __forceinline__ uint32_t smem_u32(const void* p) {
    uint32_t a;
    asm("{ .reg .u64 t; cvta.to.shared.u64 t, %1; cvt.u32.u64 %0, t; }"
        : "=r"(a) : "l"(p));
    return a;
}

#define CP_ASYNC16(dst, src) \
    asm volatile("cp.async.cg.shared.global [%0], [%1], 16;" :: "r"(dst), "l"(src))
#define CP_COMMIT()   asm volatile("cp.async.commit_group;" ::: "memory")
#define CP_WAIT(n)    asm volatile("cp.async.wait_group %0;" :: "n"(n) : "memory")

#define LDM_X4(r0, r1, r2, r3, addr) \
    asm volatile("ldmatrix.sync.aligned.m8n8.x4.shared.b16 {%0,%1,%2,%3}, [%4];" \
                 : "=r"(r0), "=r"(r1), "=r"(r2), "=r"(r3) : "r"(addr))

#define MMA_BF16(c0, c1, c2, c3, a0, a1, a2, a3, b0, b1) \
    asm volatile("mma.sync.aligned.m16n8k16.row.col.f32.bf16.bf16.f32 " \
                 "{%0,%1,%2,%3}, {%4,%5,%6,%7}, {%8,%9}, {%0,%1,%2,%3};" \
                 : "+f"(c0), "+f"(c1), "+f"(c2), "+f"(c3) \
                 : "r"(a0), "r"(a1), "r"(a2), "r"(a3), "r"(b0), "r"(b1))

// exp(2*s) via exp2 polynomial on the FMA pipe (avoid MUFU throughput wall).
__device__ __forceinline__ float fast_exp_2x(float s) {
    float t = s * 2.8853900817779268f;   // 2*log2(e)
    int   i = __float2int_rn(t);
    float f = t - (float)i;
    float p = 9.6179669e-3f;
    p = fmaf(p, f, 5.5503358e-2f);
    p = fmaf(p, f, 2.4022646e-1f);
    p = fmaf(p, f, 6.9314718e-1f);
    p = fmaf(p, f, 1.0f);
    return __int_as_float((i + 127) << 23) * p;
}

// ---------------------------------------------------------------------------
// Kernel 1: normalize rows, emit bf16 z (row-major, K=128), fp32 positives.
// ---------------------------------------------------------------------------
__global__ void normalize_kernel(const float* __restrict__ p1,
                                 const float* __restrict__ p2) {
    int warp = (blockIdx.x * blockDim.x + threadIdx.x) >> 5;
    int lane = threadIdx.x & 31;
    if (warp >= BSZ) return;

    float4 a = *(const float4*)&p1[warp * D + lane * 4];
    float4 b = *(const float4*)&p2[warp * D + lane * 4];

    float ss1 = a.x*a.x + a.y*a.y + a.z*a.z + a.w*a.w;
    float ss2 = b.x*b.x + b.y*b.y + b.z*b.z + b.w*b.w;
    #pragma unroll
    for (int o = 16; o > 0; o >>= 1) {
        ss1 += __shfl_xor_sync(0xFFFFFFFFu, ss1, o);
        ss2 += __shfl_xor_sync(0xFFFFFFFFu, ss2, o);
    }
    float r1 = rsqrtf(fmaxf(ss1, 1e-16f));
    float r2 = rsqrtf(fmaxf(ss2, 1e-16f));

    float4 z1 = make_float4(a.x*r1, a.y*r1, a.z*r1, a.w*r1);
    float4 z2 = make_float4(b.x*r2, b.y*r2, b.z*r2, b.w*r2);

    __nv_bfloat162* o1 = (__nv_bfloat162*)&g_Zbf16[warp * D + lane * 4];
    __nv_bfloat162* o2 = (__nv_bfloat162*)&g_Zbf16[(warp + BSZ) * D + lane * 4];
    o1[0] = __floats2bfloat162_rn(z1.x, z1.y);
    o1[1] = __floats2bfloat162_rn(z1.z, z1.w);
    o2[0] = __floats2bfloat162_rn(z2.x, z2.y);
    o2[1] = __floats2bfloat162_rn(z2.z, z2.w);

    float d = z1.x*z2.x + z1.y*z2.y + z1.z*z2.z + z1.w*z2.w;
    #pragma unroll
    for (int o = 16; o > 0; o >>= 1)
        d += __shfl_xor_sync(0xFFFFFFFFu, d, o);
    if (lane == 0) g_pos[warp] = d;
}

// ---------------------------------------------------------------------------
// Kernel 2: bf16 HMMA (mma.sync m16n8k16) GEMM with fused exp(2*sim) rowsum.
// Per CTA: 128 rows x (TWO_B/COLSPLITS) cols, K=128 in smem, B double-buffered.
// 8 warps in 2(m) x 4(n); warp tile 64x32.
// ---------------------------------------------------------------------------
__global__ void __launch_bounds__(NTHREADS, 1) simsum_mma_kernel() {
    extern __shared__ char smem[];
    const uint32_t sbase = smem_u32(smem);
    const int tid  = threadIdx.x;
    const int wid  = tid >> 5;
    const int lane = tid & 31;
    const int wm = wid >> 2;                  // 0..1  (row half)
    const int wn = wid & 3;                   // 0..3  (col quarter)
    const int rowbase  = blockIdx.x * TM;
    const int colsplit = blockIdx.y;
    const int colbase0 = colsplit * (TWO_B / COLSPLITS);

    float* rsum = (float*)(smem + OFF_RSUM);
    if (tid < TM) rsum[tid] = 0.0f;

    // ---- load A tile (128 rows x 128 bf16) into padded smem ----
    #pragma unroll
    for (int it = 0; it < 4; ++it) {
        int idx = it * NTHREADS + tid;        // 1024 16B chunks
        int r = idx >> 3;
        int c = idx & 7;
        uint4 v = *(const uint4*)(g_Zbf16 + (rowbase + r) * D + c * 8);
        *(uint4*)(smem + OFF_A + r * LDS_BYTES + c * 16) = v;
    }

    // ---- prefetch B tile 0 ----
    #pragma unroll
    for (int it = 0; it < 4; ++it) {
        int idx = it * NTHREADS + tid;
        int r = idx >> 3;
        int c = idx & 7;
        const char* src = (const char*)(g_Zbf16 + (colbase0 + r) * D + c * 8);
        CP_ASYNC16(sbase + OFF_B0 + r * LDS_BYTES + c * 16, src);
    }
    CP_COMMIT();

    // per-lane ldmatrix base addresses (row = lane&15, khalf = lane>>4)
    const uint32_t a_base = sbase + OFF_A +
        (uint32_t)((wm * 64 + (lane & 15)) * LDS_BYTES + (lane >> 4) * 16);
    const uint32_t b_base_rel =
        (uint32_t)((wn * 32 + (lane & 15)) * LDS_BYTES + (lane >> 4) * 16);

    float rowacc[8];
    #pragma unroll
    for (int i = 0; i < 8; ++i) rowacc[i] = 0.0f;

    __syncthreads();   // A + rsum visible

    for (int t = 0; t < NTILES; ++t) {
        // prefetch next B tile into the other buffer
        if (t + 1 < NTILES) {
            int colbase = colbase0 + (t + 1) * TN;
            uint32_t bdst = sbase + (((t + 1) & 1) ? OFF_B1 : OFF_B0);
            #pragma unroll
            for (int it = 0; it < 4; ++it) {
                int idx = it * NTHREADS + tid;
                int r = idx >> 3;
                int c = idx & 7;
                const char* src = (const char*)(g_Zbf16 + (colbase + r) * D + c * 8);
                CP_ASYNC16(bdst + r * LDS_BYTES + c * 16, src);
            }
            CP_COMMIT();
            CP_WAIT(1);     // tile t's group complete
        } else {
            CP_WAIT(0);
        }
        __syncthreads();

        const uint32_t b_base = sbase + ((t & 1) ? OFF_B1 : OFF_B0) + b_base_rel;

        float c[4][4][4];
        #pragma unroll
        for (int mi = 0; mi < 4; ++mi)
            #pragma unroll
            for (int ni = 0; ni < 4; ++ni)
                #pragma unroll
                for (int q = 0; q < 4; ++q) c[mi][ni][q] = 0.0f;

        #pragma unroll
        for (int ks = 0; ks < 8; ++ks) {
            uint32_t a[4][4];
            #pragma unroll
            for (int mi = 0; mi < 4; ++mi)
                LDM_X4(a[mi][0], a[mi][1], a[mi][2], a[mi][3],
                       a_base + (uint32_t)(mi * 16 * LDS_BYTES + ks * 32));
            uint32_t b[2][4];
            #pragma unroll
            for (int nt = 0; nt < 2; ++nt)
                LDM_X4(b[nt][0], b[nt][1], b[nt][2], b[nt][3],
                       b_base + (uint32_t)(nt * 16 * LDS_BYTES + ks * 32));
            #pragma unroll
            for (int mi = 0; mi < 4; ++mi)
                #pragma unroll
                for (int ni = 0; ni < 4; ++ni)
                    MMA_BF16(c[mi][ni][0], c[mi][ni][1], c[mi][ni][2], c[mi][ni][3],
                             a[mi][0], a[mi][1], a[mi][2], a[mi][3],
                             b[ni >> 1][ni & 1], b[ni >> 1][(ni & 1) + 2]);
        }

        // epilogue: exp(2*sim) rowsums into per-lane partials
        #pragma unroll
        for (int mi = 0; mi < 4; ++mi) {
            float s0 = 0.f, s1 = 0.f;
            #pragma unroll
            for (int ni = 0; ni < 4; ++ni) {
                s0 += fast_exp_2x(c[mi][ni][0]) + fast_exp_2x(c[mi][ni][1]);
                s1 += fast_exp_2x(c[mi][ni][2]) + fast_exp_2x(c[mi][ni][3]);
            }
            rowacc[mi * 2 + 0] += s0;
            rowacc[mi * 2 + 1] += s1;
        }

        __syncthreads();   // done reading B[t&1] before it is overwritten
    }

    // ---- reduce across the 4 lanes sharing a row (tid4 groups) ----
    #pragma unroll
    for (int i = 0; i < 8; ++i) {
        rowacc[i] += __shfl_xor_sync(0xFFFFFFFFu, rowacc[i], 1);
        rowacc[i] += __shfl_xor_sync(0xFFFFFFFFu, rowacc[i], 2);
    }
    const int groupid = lane >> 2;
    if ((lane & 3) == 0) {
        #pragma unroll
        for (int mi = 0; mi < 4; ++mi) {
            atomicAdd(&rsum[wm * 64 + mi * 16 + 0 + groupid], rowacc[mi * 2 + 0]);
            atomicAdd(&rsum[wm * 64 + mi * 16 + 8 + groupid], rowacc[mi * 2 + 1]);
        }
    }
    __syncthreads();
    if (tid < TM)
        g_partial[colsplit * TWO_B + rowbase + tid] = rsum[tid];
}

// ---------------------------------------------------------------------------
// Kernel 3: loss = mean_r( log(denom_r) - 2*pos_{r mod B} )
// ---------------------------------------------------------------------------
__global__ void finalize_kernel(float* __restrict__ out) {
    __shared__ float red[256];
    int tid = threadIdx.x;
    float s = 0.0f;
    for (int r = tid; r < TWO_B; r += 256) {
        float denom = g_partial[r] + g_partial[TWO_B + r] - 7.3890560989306495f;
        float pos = g_pos[r & (BSZ - 1)];
        s += __logf(denom) - 2.0f * pos;
    }
    red[tid] = s;
    __syncthreads();
    #pragma unroll
    for (int st = 128; st > 0; st >>= 1) {
        if (tid < st) red[tid] += red[tid + st];
        __syncthreads();
    }
    if (tid == 0) out[0] = red[0] / (float)TWO_B;
}

// ---------------------------------------------------------------------------
extern "C" void kernel_launch(void* const* d_in, const int* in_sizes, int n_in,
                              void* d_out, int out_size) {
    const float* p1 = (const float*)d_in[0];
    const float* p2 = (const float*)d_in[1];
    float* out = (float*)d_out;
    (void)in_sizes; (void)n_in; (void)out_size;

    cudaFuncSetAttribute(simsum_mma_kernel,
                         cudaFuncAttributeMaxDynamicSharedMemorySize,
                         SMEM_TOTAL);

    normalize_kernel<<<BSZ / 8, 256>>>(p1, p2);
    simsum_mma_kernel<<<dim3(TWO_B / TM, COLSPLITS), NTHREADS, SMEM_TOTAL>>>();
    finalize_kernel<<<1, 256>>>(out);
}

// round 5
// speedup vs baseline: 6.6024x; 1.2900x over previous
#include <cuda_runtime.h>
#include <cuda_bf16.h>
#include <cstdint>

#define BSZ 4096
#define D 128
#define TWO_B 8192
#define COLSPLITS 2
#define TM 128          // rows per CTA
#define TN 128          // cols per tile
#define NTHREADS 256
#define NTILES (TWO_B / COLSPLITS / TN)   // 32

// padded smem row stride: 136 bf16 = 272 B = 17 x 16B -> conflict-free ldmatrix
#define LDS_ELEM 136
#define LDS_BYTES (LDS_ELEM * 2)          // 272
#define TILE_BYTES (128 * LDS_BYTES)      // 34816

#define OFF_A    0
#define OFF_B0   TILE_BYTES
#define OFF_B1   (2 * TILE_BYTES)
#define OFF_RSUM (3 * TILE_BYTES)
#define SMEM_TOTAL (OFF_RSUM + TM * 4)

#define EXP_SCALE 2.8853900817779268f     // 2*log2(e): exp(2s) = ex2(s*EXP_SCALE)

// ---------------- device scratch ----------------
__device__ __align__(256) __nv_bfloat16 g_Zbf16[TWO_B * D];   // B side (plain z)
__device__ __align__(256) __nv_bfloat16 g_Zbf16s[TWO_B * D];  // A side (z * EXP_SCALE)
__device__ float g_pos[BSZ];
__device__ float g_partial[COLSPLITS * TWO_B];

static __device__ __forceinline__ uint32_t smem_u32(const void* p) {
    uint32_t a;
    asm("{ .reg .u64 t; cvta.to.shared.u64 t, %1; cvt.u32.u64 %0, t; }"
        : "=r"(a) : "l"(p));
    return a;
}

#define CP_ASYNC16(dst, src) \
    asm volatile("cp.async.cg.shared.global [%0], [%1], 16;" :: "r"(dst), "l"(src))
#define CP_COMMIT()   asm volatile("cp.async.commit_group;" ::: "memory")
#define CP_WAIT(n)    asm volatile("cp.async.wait_group %0;" :: "n"(n) : "memory")

#define LDM_X4(r0, r1, r2, r3, addr) \
    asm volatile("ldmatrix.sync.aligned.m8n8.x4.shared.b16 {%0,%1,%2,%3}, [%4];" \
                 : "=r"(r0), "=r"(r1), "=r"(r2), "=r"(r3) : "r"(addr))

#define MMA_BF16(c0, c1, c2, c3, a0, a1, a2, a3, b0, b1) \
    asm volatile("mma.sync.aligned.m16n8k16.row.col.f32.bf16.bf16.f32 " \
                 "{%0,%1,%2,%3}, {%4,%5,%6,%7}, {%8,%9}, {%0,%1,%2,%3};" \
                 : "+f"(c0), "+f"(c1), "+f"(c2), "+f"(c3) \
                 : "r"(a0), "r"(a1), "r"(a2), "r"(a3), "r"(b0), "r"(b1))

static __device__ __forceinline__ float ex2f(float x) {
    float r;
    asm("ex2.approx.ftz.f32 %0, %1;" : "=f"(r) : "f"(x));
    return r;
}

// ---------------------------------------------------------------------------
// Kernel 1: normalize rows; emit plain bf16 z (B side), scaled bf16 z (A side),
// fp32 positives.
// ---------------------------------------------------------------------------
__global__ void normalize_kernel(const float* __restrict__ p1,
                                 const float* __restrict__ p2) {
    int warp = (blockIdx.x * blockDim.x + threadIdx.x) >> 5;
    int lane = threadIdx.x & 31;
    if (warp >= BSZ) return;

    float4 a = *(const float4*)&p1[warp * D + lane * 4];
    float4 b = *(const float4*)&p2[warp * D + lane * 4];

    float ss1 = a.x*a.x + a.y*a.y + a.z*a.z + a.w*a.w;
    float ss2 = b.x*b.x + b.y*b.y + b.z*b.z + b.w*b.w;
    #pragma unroll
    for (int o = 16; o > 0; o >>= 1) {
        ss1 += __shfl_xor_sync(0xFFFFFFFFu, ss1, o);
        ss2 += __shfl_xor_sync(0xFFFFFFFFu, ss2, o);
    }
    float r1 = rsqrtf(fmaxf(ss1, 1e-16f));
    float r2 = rsqrtf(fmaxf(ss2, 1e-16f));

    float4 z1 = make_float4(a.x*r1, a.y*r1, a.z*r1, a.w*r1);
    float4 z2 = make_float4(b.x*r2, b.y*r2, b.z*r2, b.w*r2);

    __nv_bfloat162* o1 = (__nv_bfloat162*)&g_Zbf16[warp * D + lane * 4];
    __nv_bfloat162* o2 = (__nv_bfloat162*)&g_Zbf16[(warp + BSZ) * D + lane * 4];
    o1[0] = __floats2bfloat162_rn(z1.x, z1.y);
    o1[1] = __floats2bfloat162_rn(z1.z, z1.w);
    o2[0] = __floats2bfloat162_rn(z2.x, z2.y);
    o2[1] = __floats2bfloat162_rn(z2.z, z2.w);

    __nv_bfloat162* s1 = (__nv_bfloat162*)&g_Zbf16s[warp * D + lane * 4];
    __nv_bfloat162* s2 = (__nv_bfloat162*)&g_Zbf16s[(warp + BSZ) * D + lane * 4];
    s1[0] = __floats2bfloat162_rn(z1.x * EXP_SCALE, z1.y * EXP_SCALE);
    s1[1] = __floats2bfloat162_rn(z1.z * EXP_SCALE, z1.w * EXP_SCALE);
    s2[0] = __floats2bfloat162_rn(z2.x * EXP_SCALE, z2.y * EXP_SCALE);
    s2[1] = __floats2bfloat162_rn(z2.z * EXP_SCALE, z2.w * EXP_SCALE);

    float d = z1.x*z2.x + z1.y*z2.y + z1.z*z2.z + z1.w*z2.w;
    #pragma unroll
    for (int o = 16; o > 0; o >>= 1)
        d += __shfl_xor_sync(0xFFFFFFFFu, d, o);
    if (lane == 0) g_pos[warp] = d;
}

// ---------------------------------------------------------------------------
// Kernel 2: bf16 HMMA GEMM with fused ex2 rowsum epilogue.
// A fragments (scaled z rows) cached in registers across all 32 column tiles.
// MMA outputs t = 2*log2(e)*sim; epilogue is MUFU ex2 + FADD only.
// ---------------------------------------------------------------------------
__global__ void __launch_bounds__(NTHREADS, 1) simsum_mma_kernel() {
    extern __shared__ char smem[];
    const uint32_t sbase = smem_u32(smem);
    const int tid  = threadIdx.x;
    const int wid  = tid >> 5;
    const int lane = tid & 31;
    const int wm = wid >> 2;                  // 0..1  (row half)
    const int wn = wid & 3;                   // 0..3  (col quarter)
    const int rowbase  = blockIdx.x * TM;
    const int colsplit = blockIdx.y;
    const int colbase0 = colsplit * (TWO_B / COLSPLITS);

    float* rsum = (float*)(smem + OFF_RSUM);
    if (tid < TM) rsum[tid] = 0.0f;

    // ---- load A tile (scaled) into padded smem ----
    #pragma unroll
    for (int it = 0; it < 4; ++it) {
        int idx = it * NTHREADS + tid;        // 1024 16B chunks
        int r = idx >> 3;
        int c = idx & 7;
        uint4 v = *(const uint4*)(g_Zbf16s + (rowbase + r) * D + c * 8);
        *(uint4*)(smem + OFF_A + r * LDS_BYTES + c * 16) = v;
    }

    // ---- prefetch B tile 0 ----
    #pragma unroll
    for (int it = 0; it < 4; ++it) {
        int idx = it * NTHREADS + tid;
        int r = idx >> 3;
        int c = idx & 7;
        const char* src = (const char*)(g_Zbf16 + (colbase0 + r) * D + c * 8);
        CP_ASYNC16(sbase + OFF_B0 + r * LDS_BYTES + c * 16, src);
    }
    CP_COMMIT();

    const uint32_t a_base = sbase + OFF_A +
        (uint32_t)((wm * 64 + (lane & 15)) * LDS_BYTES + (lane >> 4) * 16);
    const uint32_t b_base_rel =
        (uint32_t)((wn * 32 + (lane & 15)) * LDS_BYTES + (lane >> 4) * 16);

    __syncthreads();   // A + rsum visible

    // ---- cache all A fragments in registers: 8 ksteps x 4 mtiles x 4 regs ----
    uint32_t afr[8][4][4];
    #pragma unroll
    for (int ks = 0; ks < 8; ++ks)
        #pragma unroll
        for (int mi = 0; mi < 4; ++mi)
            LDM_X4(afr[ks][mi][0], afr[ks][mi][1], afr[ks][mi][2], afr[ks][mi][3],
                   a_base + (uint32_t)(mi * 16 * LDS_BYTES + ks * 32));

    float rowacc[8];
    #pragma unroll
    for (int i = 0; i < 8; ++i) rowacc[i] = 0.0f;

    for (int t = 0; t < NTILES; ++t) {
        // prefetch next B tile into the other buffer
        if (t + 1 < NTILES) {
            int colbase = colbase0 + (t + 1) * TN;
            uint32_t bdst = sbase + (((t + 1) & 1) ? OFF_B1 : OFF_B0);
            #pragma unroll
            for (int it = 0; it < 4; ++it) {
                int idx = it * NTHREADS + tid;
                int r = idx >> 3;
                int c = idx & 7;
                const char* src = (const char*)(g_Zbf16 + (colbase + r) * D + c * 8);
                CP_ASYNC16(bdst + r * LDS_BYTES + c * 16, src);
            }
            CP_COMMIT();
            CP_WAIT(1);
        } else {
            CP_WAIT(0);
        }
        __syncthreads();

        const uint32_t b_base = sbase + ((t & 1) ? OFF_B1 : OFF_B0) + b_base_rel;

        float c[4][4][4];
        #pragma unroll
        for (int mi = 0; mi < 4; ++mi)
            #pragma unroll
            for (int ni = 0; ni < 4; ++ni)
                #pragma unroll
                for (int q = 0; q < 4; ++q) c[mi][ni][q] = 0.0f;

        #pragma unroll
        for (int ks = 0; ks < 8; ++ks) {
            uint32_t b[2][4];
            #pragma unroll
            for (int nt = 0; nt < 2; ++nt)
                LDM_X4(b[nt][0], b[nt][1], b[nt][2], b[nt][3],
                       b_base + (uint32_t)(nt * 16 * LDS_BYTES + ks * 32));
            #pragma unroll
            for (int mi = 0; mi < 4; ++mi)
                #pragma unroll
                for (int ni = 0; ni < 4; ++ni)
                    MMA_BF16(c[mi][ni][0], c[mi][ni][1], c[mi][ni][2], c[mi][ni][3],
                             afr[ks][mi][0], afr[ks][mi][1], afr[ks][mi][2], afr[ks][mi][3],
                             b[ni >> 1][ni & 1], b[ni >> 1][(ni & 1) + 2]);
        }

        // epilogue: ex2 (MUFU pipe) + FADD rowsums
        #pragma unroll
        for (int mi = 0; mi < 4; ++mi) {
            float s0 = 0.f, s1 = 0.f;
            #pragma unroll
            for (int ni = 0; ni < 4; ++ni) {
                s0 += ex2f(c[mi][ni][0]) + ex2f(c[mi][ni][1]);
                s1 += ex2f(c[mi][ni][2]) + ex2f(c[mi][ni][3]);
            }
            rowacc[mi * 2 + 0] += s0;
            rowacc[mi * 2 + 1] += s1;
        }

        __syncthreads();   // done reading B[t&1] before it is overwritten
    }

    // ---- reduce across the 4 lanes sharing a row ----
    #pragma unroll
    for (int i = 0; i < 8; ++i) {
        rowacc[i] += __shfl_xor_sync(0xFFFFFFFFu, rowacc[i], 1);
        rowacc[i] += __shfl_xor_sync(0xFFFFFFFFu, rowacc[i], 2);
    }
    const int groupid = lane >> 2;
    if ((lane & 3) == 0) {
        #pragma unroll
        for (int mi = 0; mi < 4; ++mi) {
            atomicAdd(&rsum[wm * 64 + mi * 16 + 0 + groupid], rowacc[mi * 2 + 0]);
            atomicAdd(&rsum[wm * 64 + mi * 16 + 8 + groupid], rowacc[mi * 2 + 1]);
        }
    }
    __syncthreads();
    if (tid < TM)
        g_partial[colsplit * TWO_B + rowbase + tid] = rsum[tid];
}

// ---------------------------------------------------------------------------
// Kernel 3: loss = mean_r( log(denom_r) - 2*pos_{r mod B} )
// ---------------------------------------------------------------------------
__global__ void finalize_kernel(float* __restrict__ out) {
    __shared__ float red[1024];
    int tid = threadIdx.x;
    float s = 0.0f;
    for (int r = tid; r < TWO_B; r += 1024) {
        float denom = g_partial[r] + g_partial[TWO_B + r] - 7.3890560989306495f;
        float pos = g_pos[r & (BSZ - 1)];
        s += __logf(denom) - 2.0f * pos;
    }
    red[tid] = s;
    __syncthreads();
    #pragma unroll
    for (int st = 512; st > 0; st >>= 1) {
        if (tid < st) red[tid] += red[tid + st];
        __syncthreads();
    }
    if (tid == 0) out[0] = red[0] / (float)TWO_B;
}

// ---------------------------------------------------------------------------
extern "C" void kernel_launch(void* const* d_in, const int* in_sizes, int n_in,
                              void* d_out, int out_size) {
    const float* p1 = (const float*)d_in[0];
    const float* p2 = (const float*)d_in[1];
    float* out = (float*)d_out;
    (void)in_sizes; (void)n_in; (void)out_size;

    cudaFuncSetAttribute(simsum_mma_kernel,
                         cudaFuncAttributeMaxDynamicSharedMemorySize,
                         SMEM_TOTAL);

    normalize_kernel<<<BSZ / 8, 256>>>(p1, p2);
    simsum_mma_kernel<<<dim3(TWO_B / TM, COLSPLITS), NTHREADS, SMEM_TOTAL>>>();
    finalize_kernel<<<1, 1024>>>(out);
}

// round 6
// speedup vs baseline: 9.6328x; 1.4590x over previous
#include <cuda_runtime.h>
#include <cuda_bf16.h>
#include <cstdint>

#define BSZ 4096
#define D 128
#define TWO_B 8192
#define NRB 64                         // 64 row/col blocks of 128
#define NTHREADS 256
#define NTILES_TRI 2080                // 64*65/2

// padded smem row stride: 136 bf16 = 272 B -> conflict-free ldmatrix
#define LDS_ELEM 136
#define LDS_BYTES (LDS_ELEM * 2)
#define TILE_BYTES (128 * LDS_BYTES)   // 34816

#define OFF_A    0
#define OFF_B0   TILE_BYTES
#define OFF_B1   (2 * TILE_BYTES)
#define SMEM_TOTAL (3 * TILE_BYTES)

#define EXP_SCALE 2.8853900817779268f  // 2*log2(e): exp(2s) = ex2(s*EXP_SCALE)

// ---------------- device scratch ----------------
__device__ __align__(256) __nv_bfloat16 g_Zbf16[TWO_B * D];   // B side (plain z)
__device__ __align__(256) __nv_bfloat16 g_Zbf16s[TWO_B * D];  // A side (z * EXP_SCALE)
__device__ float g_pos[BSZ];
__device__ float g_denom[TWO_B];       // atomically accumulated exp-rowsums

static __device__ __forceinline__ uint32_t smem_u32(const void* p) {
    uint32_t a;
    asm("{ .reg .u64 t; cvta.to.shared.u64 t, %1; cvt.u32.u64 %0, t; }"
        : "=r"(a) : "l"(p));
    return a;
}

#define CP_ASYNC16(dst, src) \
    asm volatile("cp.async.cg.shared.global [%0], [%1], 16;" :: "r"(dst), "l"(src))
#define CP_COMMIT()   asm volatile("cp.async.commit_group;" ::: "memory")
#define CP_WAIT(n)    asm volatile("cp.async.wait_group %0;" :: "n"(n) : "memory")

#define LDM_X4(r0, r1, r2, r3, addr) \
    asm volatile("ldmatrix.sync.aligned.m8n8.x4.shared.b16 {%0,%1,%2,%3}, [%4];" \
                 : "=r"(r0), "=r"(r1), "=r"(r2), "=r"(r3) : "r"(addr))

#define MMA_BF16(c0, c1, c2, c3, a0, a1, a2, a3, b0, b1) \
    asm volatile("mma.sync.aligned.m16n8k16.row.col.f32.bf16.bf16.f32 " \
                 "{%0,%1,%2,%3}, {%4,%5,%6,%7}, {%8,%9}, {%0,%1,%2,%3};" \
                 : "+f"(c0), "+f"(c1), "+f"(c2), "+f"(c3) \
                 : "r"(a0), "r"(a1), "r"(a2), "r"(a3), "r"(b0), "r"(b1))

static __device__ __forceinline__ float ex2f(float x) {
    float r;
    asm("ex2.approx.ftz.f32 %0, %1;" : "=f"(r) : "f"(x));
    return r;
}

// ---------------------------------------------------------------------------
// Kernel 1: normalize; emit plain bf16 z (B side) + scaled bf16 z (A side),
// fp32 positives; zero g_denom.
// ---------------------------------------------------------------------------
__global__ void normalize_kernel(const float* __restrict__ p1,
                                 const float* __restrict__ p2) {
    int gid  = blockIdx.x * blockDim.x + threadIdx.x;
    if (gid < TWO_B) g_denom[gid] = 0.0f;

    int warp = gid >> 5;
    int lane = threadIdx.x & 31;
    if (warp >= BSZ) return;

    float4 a = *(const float4*)&p1[warp * D + lane * 4];
    float4 b = *(const float4*)&p2[warp * D + lane * 4];

    float ss1 = a.x*a.x + a.y*a.y + a.z*a.z + a.w*a.w;
    float ss2 = b.x*b.x + b.y*b.y + b.z*b.z + b.w*b.w;
    #pragma unroll
    for (int o = 16; o > 0; o >>= 1) {
        ss1 += __shfl_xor_sync(0xFFFFFFFFu, ss1, o);
        ss2 += __shfl_xor_sync(0xFFFFFFFFu, ss2, o);
    }
    float r1 = rsqrtf(fmaxf(ss1, 1e-16f));
    float r2 = rsqrtf(fmaxf(ss2, 1e-16f));

    float4 z1 = make_float4(a.x*r1, a.y*r1, a.z*r1, a.w*r1);
    float4 z2 = make_float4(b.x*r2, b.y*r2, b.z*r2, b.w*r2);

    __nv_bfloat162* o1 = (__nv_bfloat162*)&g_Zbf16[warp * D + lane * 4];
    __nv_bfloat162* o2 = (__nv_bfloat162*)&g_Zbf16[(warp + BSZ) * D + lane * 4];
    o1[0] = __floats2bfloat162_rn(z1.x, z1.y);
    o1[1] = __floats2bfloat162_rn(z1.z, z1.w);
    o2[0] = __floats2bfloat162_rn(z2.x, z2.y);
    o2[1] = __floats2bfloat162_rn(z2.z, z2.w);

    __nv_bfloat162* s1 = (__nv_bfloat162*)&g_Zbf16s[warp * D + lane * 4];
    __nv_bfloat162* s2 = (__nv_bfloat162*)&g_Zbf16s[(warp + BSZ) * D + lane * 4];
    s1[0] = __floats2bfloat162_rn(z1.x * EXP_SCALE, z1.y * EXP_SCALE);
    s1[1] = __floats2bfloat162_rn(z1.z * EXP_SCALE, z1.w * EXP_SCALE);
    s2[0] = __floats2bfloat162_rn(z2.x * EXP_SCALE, z2.y * EXP_SCALE);
    s2[1] = __floats2bfloat162_rn(z2.z * EXP_SCALE, z2.w * EXP_SCALE);

    float d = z1.x*z2.x + z1.y*z2.y + z1.z*z2.z + z1.w*z2.w;
    #pragma unroll
    for (int o = 16; o > 0; o >>= 1)
        d += __shfl_xor_sync(0xFFFFFFFFu, d, o);
    if (lane == 0) g_pos[warp] = d;
}

// ---------------------------------------------------------------------------
// Kernel 2: upper-triangle bf16 HMMA with fused ex2; each off-diagonal tile
// feeds rowsums (block r) AND colsums (block j) of g_denom. 148 CTAs each
// process 14-15 contiguous triangle-linear tiles.
// ---------------------------------------------------------------------------
__global__ void __launch_bounds__(NTHREADS, 1) simsum_tri_kernel() {
    extern __shared__ char smem[];
    const uint32_t sbase = smem_u32(smem);
    const int tid  = threadIdx.x;
    const int wid  = tid >> 5;
    const int lane = tid & 31;
    const int wm = wid >> 2;                  // 0..1 (row half)
    const int wn = wid & 3;                   // 0..3 (col quarter)
    const int bid = blockIdx.x;

    // chunk assignment: 2080 = 8*15 + 140*14
    const int cnt   = 14 + (bid < 8 ? 1 : 0);
    const int start = bid * 14 + (bid < 8 ? bid : 8);

    // map start -> (r, j) in triangle (row-major, j >= r); off(r) = r*(129-r)/2
    int r;
    {
        float fr = (129.0f - sqrtf(129.0f * 129.0f - 8.0f * (float)start)) * 0.5f;
        r = (int)fr;
        if (r < 0) r = 0;
        if (r > 63) r = 63;
        while (r < 63 && (r + 1) * (129 - (r + 1)) / 2 <= start) ++r;
        while (r > 0 && r * (129 - r) / 2 > start) --r;
    }
    int j = r + (start - r * (129 - r) / 2);

    const uint32_t a_base = sbase + OFF_A +
        (uint32_t)((wm * 64 + (lane & 15)) * LDS_BYTES + (lane >> 4) * 16);
    const uint32_t b_base_rel =
        (uint32_t)((wn * 32 + (lane & 15)) * LDS_BYTES + (lane >> 4) * 16);
    const int groupid = lane >> 2;

    // ---- prefetch B tile for j ----
    #pragma unroll
    for (int it = 0; it < 4; ++it) {
        int idx = it * NTHREADS + tid;
        int rr = idx >> 3, cc = idx & 7;
        const char* src = (const char*)(g_Zbf16 + (j * 128 + rr) * D + cc * 8);
        CP_ASYNC16(sbase + OFF_B0 + rr * LDS_BYTES + cc * 16, src);
    }
    CP_COMMIT();

    // ---- load A tile for r (plain LDG/STS) + ldmatrix into registers ----
    uint32_t afr[8][4][4];
    {
        #pragma unroll
        for (int it = 0; it < 4; ++it) {
            int idx = it * NTHREADS + tid;
            int rr = idx >> 3, cc = idx & 7;
            uint4 v = *(const uint4*)(g_Zbf16s + (r * 128 + rr) * D + cc * 8);
            *(uint4*)(smem + OFF_A + rr * LDS_BYTES + cc * 16) = v;
        }
        __syncthreads();
        #pragma unroll
        for (int ks = 0; ks < 8; ++ks)
            #pragma unroll
            for (int mi = 0; mi < 4; ++mi)
                LDM_X4(afr[ks][mi][0], afr[ks][mi][1], afr[ks][mi][2], afr[ks][mi][3],
                       a_base + (uint32_t)(mi * 16 * LDS_BYTES + ks * 32));
    }

    float rowacc[8];
    #pragma unroll
    for (int i = 0; i < 8; ++i) rowacc[i] = 0.0f;

    for (int t = 0; t < cnt; ++t) {
        // next tile indices
        int rn = r, jn = j + 1;
        if (jn >= NRB) { rn = r + 1; jn = rn; }

        // prefetch B for next tile
        if (t + 1 < cnt) {
            uint32_t bdst = sbase + (((t + 1) & 1) ? OFF_B1 : OFF_B0);
            #pragma unroll
            for (int it = 0; it < 4; ++it) {
                int idx = it * NTHREADS + tid;
                int rr = idx >> 3, cc = idx & 7;
                const char* src = (const char*)(g_Zbf16 + (jn * 128 + rr) * D + cc * 8);
                CP_ASYNC16(bdst + rr * LDS_BYTES + cc * 16, src);
            }
            CP_COMMIT();
            CP_WAIT(1);
        } else {
            CP_WAIT(0);
        }
        __syncthreads();

        const uint32_t b_base = sbase + ((t & 1) ? OFF_B1 : OFF_B0) + b_base_rel;

        float c[4][4][4];
        #pragma unroll
        for (int mi = 0; mi < 4; ++mi)
            #pragma unroll
            for (int ni = 0; ni < 4; ++ni)
                #pragma unroll
                for (int q = 0; q < 4; ++q) c[mi][ni][q] = 0.0f;

        #pragma unroll
        for (int ks = 0; ks < 8; ++ks) {
            uint32_t b[2][4];
            #pragma unroll
            for (int nt = 0; nt < 2; ++nt)
                LDM_X4(b[nt][0], b[nt][1], b[nt][2], b[nt][3],
                       b_base + (uint32_t)(nt * 16 * LDS_BYTES + ks * 32));
            #pragma unroll
            for (int mi = 0; mi < 4; ++mi)
                #pragma unroll
                for (int ni = 0; ni < 4; ++ni)
                    MMA_BF16(c[mi][ni][0], c[mi][ni][1], c[mi][ni][2], c[mi][ni][3],
                             afr[ks][mi][0], afr[ks][mi][1], afr[ks][mi][2], afr[ks][mi][3],
                             b[ni >> 1][ni & 1], b[ni >> 1][(ni & 1) + 2]);
        }

        // epilogue: ex2 (MUFU) -> rowacc + per-tile colacc
        float colacc[8];
        #pragma unroll
        for (int i = 0; i < 8; ++i) colacc[i] = 0.0f;

        #pragma unroll
        for (int mi = 0; mi < 4; ++mi)
            #pragma unroll
            for (int ni = 0; ni < 4; ++ni) {
                float e0 = ex2f(c[mi][ni][0]);
                float e1 = ex2f(c[mi][ni][1]);
                float e2 = ex2f(c[mi][ni][2]);
                float e3 = ex2f(c[mi][ni][3]);
                rowacc[mi * 2 + 0] += e0 + e1;
                rowacc[mi * 2 + 1] += e2 + e3;
                colacc[ni * 2 + 0] += e0 + e2;
                colacc[ni * 2 + 1] += e1 + e3;
            }

        // flush colsums (transpose contribution) unless on the diagonal
        if (j != r) {
            #pragma unroll
            for (int i = 0; i < 8; ++i) {
                colacc[i] += __shfl_xor_sync(0xFFFFFFFFu, colacc[i], 4);
                colacc[i] += __shfl_xor_sync(0xFFFFFFFFu, colacc[i], 8);
                colacc[i] += __shfl_xor_sync(0xFFFFFFFFu, colacc[i], 16);
            }
            if (lane < 4) {
                int cb = j * 128 + wn * 32 + 2 * lane;
                #pragma unroll
                for (int ni = 0; ni < 4; ++ni) {
                    atomicAdd(&g_denom[cb + ni * 8 + 0], colacc[ni * 2 + 0]);
                    atomicAdd(&g_denom[cb + ni * 8 + 1], colacc[ni * 2 + 1]);
                }
            }
        }

        __syncthreads();   // B buffer reuse guard

        // strip change: flush rowsums, reload A for rn
        if (t + 1 < cnt && rn != r) {
            #pragma unroll
            for (int i = 0; i < 8; ++i) {
                rowacc[i] += __shfl_xor_sync(0xFFFFFFFFu, rowacc[i], 1);
                rowacc[i] += __shfl_xor_sync(0xFFFFFFFFu, rowacc[i], 2);
            }
            if ((lane & 3) == 0) {
                int rb = r * 128 + wm * 64 + groupid;
                #pragma unroll
                for (int mi = 0; mi < 4; ++mi) {
                    atomicAdd(&g_denom[rb + mi * 16 + 0], rowacc[mi * 2 + 0]);
                    atomicAdd(&g_denom[rb + mi * 16 + 8], rowacc[mi * 2 + 1]);
                }
            }
            #pragma unroll
            for (int i = 0; i < 8; ++i) rowacc[i] = 0.0f;

            #pragma unroll
            for (int it = 0; it < 4; ++it) {
                int idx = it * NTHREADS + tid;
                int rr = idx >> 3, cc = idx & 7;
                uint4 v = *(const uint4*)(g_Zbf16s + (rn * 128 + rr) * D + cc * 8);
                *(uint4*)(smem + OFF_A + rr * LDS_BYTES + cc * 16) = v;
            }
            __syncthreads();
            #pragma unroll
            for (int ks = 0; ks < 8; ++ks)
                #pragma unroll
                for (int mi = 0; mi < 4; ++mi)
                    LDM_X4(afr[ks][mi][0], afr[ks][mi][1], afr[ks][mi][2], afr[ks][mi][3],
                           a_base + (uint32_t)(mi * 16 * LDS_BYTES + ks * 32));
        }

        r = rn; j = jn;
    }

    // final rowsum flush
    #pragma unroll
    for (int i = 0; i < 8; ++i) {
        rowacc[i] += __shfl_xor_sync(0xFFFFFFFFu, rowacc[i], 1);
        rowacc[i] += __shfl_xor_sync(0xFFFFFFFFu, rowacc[i], 2);
    }
    if ((lane & 3) == 0) {
        // r holds the last processed strip (rn==r after final iteration step)
        int lastr = r;
        if (j >= NRB) lastr = r;   // no-op; indices already advanced consistently
        // note: after loop, (r,j) point one past; last processed strip is:
        // if j == r (wrapped), last strip was r-1 ... recover from start+cnt-1
        int lastidx = start + cnt - 1;
        int rr2;
        {
            float fr = (129.0f - sqrtf(129.0f * 129.0f - 8.0f * (float)lastidx)) * 0.5f;
            rr2 = (int)fr;
            if (rr2 < 0) rr2 = 0;
            if (rr2 > 63) rr2 = 63;
            while (rr2 < 63 && (rr2 + 1) * (129 - (rr2 + 1)) / 2 <= lastidx) ++rr2;
            while (rr2 > 0 && rr2 * (129 - rr2) / 2 > lastidx) --rr2;
        }
        int rb = rr2 * 128 + wm * 64 + groupid;
        #pragma unroll
        for (int mi = 0; mi < 4; ++mi) {
            atomicAdd(&g_denom[rb + mi * 16 + 0], rowacc[mi * 2 + 0]);
            atomicAdd(&g_denom[rb + mi * 16 + 8], rowacc[mi * 2 + 1]);
        }
    }
}

// ---------------------------------------------------------------------------
// Kernel 3: loss = mean_r( log(denom_r) - 2*pos_{r mod B} )
// ---------------------------------------------------------------------------
__global__ void finalize_kernel(float* __restrict__ out) {
    __shared__ float red[1024];
    int tid = threadIdx.x;
    float s = 0.0f;
    for (int r = tid; r < TWO_B; r += 1024) {
        float denom = g_denom[r] - 7.3890560989306495f;
        float pos = g_pos[r & (BSZ - 1)];
        s += __logf(denom) - 2.0f * pos;
    }
    red[tid] = s;
    __syncthreads();
    #pragma unroll
    for (int st = 512; st > 0; st >>= 1) {
        if (tid < st) red[tid] += red[tid + st];
        __syncthreads();
    }
    if (tid == 0) out[0] = red[0] / (float)TWO_B;
}

// ---------------------------------------------------------------------------
extern "C" void kernel_launch(void* const* d_in, const int* in_sizes, int n_in,
                              void* d_out, int out_size) {
    const float* p1 = (const float*)d_in[0];
    const float* p2 = (const float*)d_in[1];
    float* out = (float*)d_out;
    (void)in_sizes; (void)n_in; (void)out_size;

    cudaFuncSetAttribute(simsum_tri_kernel,
                         cudaFuncAttributeMaxDynamicSharedMemorySize,
                         SMEM_TOTAL);

    normalize_kernel<<<BSZ / 8, 256>>>(p1, p2);
    simsum_tri_kernel<<<148, NTHREADS, SMEM_TOTAL>>>();
    finalize_kernel<<<1, 1024>>>(out);
}

// round 7
// speedup vs baseline: 10.0176x; 1.0399x over previous
#include <cuda_runtime.h>
#include <cuda_bf16.h>
#include <cstdint>

#define BSZ 4096
#define D 128
#define TWO_B 8192
#define NRB 64
#define NTHREADS 256
#define NCTAS 148

#define LDS_ELEM 136
#define LDS_BYTES (LDS_ELEM * 2)
#define TILE_BYTES (128 * LDS_BYTES)

#define OFF_A    0
#define OFF_B0   TILE_BYTES
#define OFF_B1   (2 * TILE_BYTES)
#define SMEM_TOTAL (3 * TILE_BYTES)

#define EXP_SCALE 2.8853900817779268f   // 2*log2(e): exp(2s) = ex2(s*EXP_SCALE)

__device__ __align__(256) __nv_bfloat16 g_Zbf16[TWO_B * D];
__device__ float g_pos[BSZ];
__device__ float g_denom[TWO_B];
__device__ unsigned int g_done = 0;

static __device__ __forceinline__ uint32_t smem_u32(const void* p) {
    uint32_t a;
    asm("{ .reg .u64 t; cvta.to.shared.u64 t, %1; cvt.u32.u64 %0, t; }"
        : "=r"(a) : "l"(p));
    return a;
}

#define CP_ASYNC16(dst, src) \
    asm volatile("cp.async.cg.shared.global [%0], [%1], 16;" :: "r"(dst), "l"(src))
#define CP_COMMIT()   asm volatile("cp.async.commit_group;" ::: "memory")
#define CP_WAIT(n)    asm volatile("cp.async.wait_group %0;" :: "n"(n) : "memory")

#define LDM_X4(r0, r1, r2, r3, addr) \
    asm volatile("ldmatrix.sync.aligned.m8n8.x4.shared.b16 {%0,%1,%2,%3}, [%4];" \
                 : "=r"(r0), "=r"(r1), "=r"(r2), "=r"(r3) : "r"(addr))

#define MMA_BF16(c0, c1, c2, c3, a0, a1, a2, a3, b0, b1) \
    asm volatile("mma.sync.aligned.m16n8k16.row.col.f32.bf16.bf16.f32 " \
                 "{%0,%1,%2,%3}, {%4,%5,%6,%7}, {%8,%9}, {%0,%1,%2,%3};" \
                 : "+f"(c0), "+f"(c1), "+f"(c2), "+f"(c3) \
                 : "r"(a0), "r"(a1), "r"(a2), "r"(a3), "r"(b0), "r"(b1))

static __device__ __forceinline__ float ex2f(float x) {
    float r;
    asm("ex2.approx.ftz.f32 %0, %1;" : "=f"(r) : "f"(x));
    return r;
}

// ---------------------------------------------------------------------------
// Kernel 1: normalize; emit bf16 z; fp32 positives; zero g_denom.
// ---------------------------------------------------------------------------
__global__ void normalize_kernel(const float* __restrict__ p1,
                                 const float* __restrict__ p2) {
    int gid  = blockIdx.x * blockDim.x + threadIdx.x;
    if (gid < TWO_B) g_denom[gid] = 0.0f;

    int warp = gid >> 5;
    int lane = threadIdx.x & 31;
    if (warp >= BSZ) return;

    float4 a = *(const float4*)&p1[warp * D + lane * 4];
    float4 b = *(const float4*)&p2[warp * D + lane * 4];

    float ss1 = a.x*a.x + a.y*a.y + a.z*a.z + a.w*a.w;
    float ss2 = b.x*b.x + b.y*b.y + b.z*b.z + b.w*b.w;
    #pragma unroll
    for (int o = 16; o > 0; o >>= 1) {
        ss1 += __shfl_xor_sync(0xFFFFFFFFu, ss1, o);
        ss2 += __shfl_xor_sync(0xFFFFFFFFu, ss2, o);
    }
    float r1 = rsqrtf(fmaxf(ss1, 1e-16f));
    float r2 = rsqrtf(fmaxf(ss2, 1e-16f));

    float4 z1 = make_float4(a.x*r1, a.y*r1, a.z*r1, a.w*r1);
    float4 z2 = make_float4(b.x*r2, b.y*r2, b.z*r2, b.w*r2);

    __nv_bfloat162* o1 = (__nv_bfloat162*)&g_Zbf16[warp * D + lane * 4];
    __nv_bfloat162* o2 = (__nv_bfloat162*)&g_Zbf16[(warp + BSZ) * D + lane * 4];
    o1[0] = __floats2bfloat162_rn(z1.x, z1.y);
    o1[1] = __floats2bfloat162_rn(z1.z, z1.w);
    o2[0] = __floats2bfloat162_rn(z2.x, z2.y);
    o2[1] = __floats2bfloat162_rn(z2.z, z2.w);

    float d = z1.x*z2.x + z1.y*z2.y + z1.z*z2.z + z1.w*z2.w;
    #pragma unroll
    for (int o = 16; o > 0; o >>= 1)
        d += __shfl_xor_sync(0xFFFFFFFFu, d, o);
    if (lane == 0) g_pos[warp] = d;
}

// process one epilogue element e (0..31) of half hf (0 or 1)
#define EPI_ELEM(hf, e) do {                                                  \
    int mi_ = (e) >> 3, ni_ = (((e) >> 2) & 1), q_ = (e) & 3;                 \
    float ev_ = ex2f(c[mi_][(hf) * 2 + ni_][q_] * EXP_SCALE);                 \
    rowacc[mi_ * 2 + (q_ >> 1)] += ev_;                                       \
    colacc[((hf) * 2 + ni_) * 2 + (q_ & 1)] += ev_;                           \
} while (0)

// ---------------------------------------------------------------------------
// Kernel 2: upper-triangle HMMA + fused ex2 rowsum/colsum + fused finalize.
// Epilogue of N-half0 interleaved into N-half1's MMA ks-loop (MUFU in issue
// shadows of the tensor pipe).
// ---------------------------------------------------------------------------
__global__ void __launch_bounds__(NTHREADS, 1) simsum_tri_kernel(float* __restrict__ out) {
    extern __shared__ char smem[];
    const uint32_t sbase = smem_u32(smem);
    const int tid  = threadIdx.x;
    const int lane = tid & 31;
    const int wid  = tid >> 5;
    const int wm = wid >> 2;
    const int wn = wid & 3;
    const int bid = blockIdx.x;

    const int cnt   = 14 + (bid < 8 ? 1 : 0);
    const int start = bid * 14 + (bid < 8 ? bid : 8);

    int r;
    {
        float fr = (129.0f - sqrtf(129.0f * 129.0f - 8.0f * (float)start)) * 0.5f;
        r = (int)fr;
        if (r < 0) r = 0;
        if (r > 63) r = 63;
        while (r < 63 && (r + 1) * (129 - (r + 1)) / 2 <= start) ++r;
        while (r > 0 && r * (129 - r) / 2 > start) --r;
    }
    int j = r + (start - r * (129 - r) / 2);

    const uint32_t a_base = sbase + OFF_A +
        (uint32_t)((wm * 64 + (lane & 15)) * LDS_BYTES + (lane >> 4) * 16);
    const uint32_t b_base_rel =
        (uint32_t)((wn * 32 + (lane & 15)) * LDS_BYTES + (lane >> 4) * 16);
    const int groupid = lane >> 2;

    // prefetch B tile for j
    #pragma unroll
    for (int it = 0; it < 4; ++it) {
        int idx = it * NTHREADS + tid;
        int rr = idx >> 3, cc = idx & 7;
        const char* src = (const char*)(g_Zbf16 + (j * 128 + rr) * D + cc * 8);
        CP_ASYNC16(sbase + OFF_B0 + rr * LDS_BYTES + cc * 16, src);
    }
    CP_COMMIT();

    // load A strip r, cache fragments
    uint32_t afr[8][4][4];
    {
        #pragma unroll
        for (int it = 0; it < 4; ++it) {
            int idx = it * NTHREADS + tid;
            int rr = idx >> 3, cc = idx & 7;
            uint4 v = *(const uint4*)(g_Zbf16 + (r * 128 + rr) * D + cc * 8);
            *(uint4*)(smem + OFF_A + rr * LDS_BYTES + cc * 16) = v;
        }
        __syncthreads();
        #pragma unroll
        for (int ks = 0; ks < 8; ++ks)
            #pragma unroll
            for (int mi = 0; mi < 4; ++mi)
                LDM_X4(afr[ks][mi][0], afr[ks][mi][1], afr[ks][mi][2], afr[ks][mi][3],
                       a_base + (uint32_t)(mi * 16 * LDS_BYTES + ks * 32));
    }

    float rowacc[8];
    #pragma unroll
    for (int i = 0; i < 8; ++i) rowacc[i] = 0.0f;

    for (int t = 0; t < cnt; ++t) {
        int rn = r, jn = j + 1;
        if (jn >= NRB) { rn = r + 1; jn = rn; }

        if (t + 1 < cnt) {
            uint32_t bdst = sbase + (((t + 1) & 1) ? OFF_B1 : OFF_B0);
            #pragma unroll
            for (int it = 0; it < 4; ++it) {
                int idx = it * NTHREADS + tid;
                int rr = idx >> 3, cc = idx & 7;
                const char* src = (const char*)(g_Zbf16 + (jn * 128 + rr) * D + cc * 8);
                CP_ASYNC16(bdst + rr * LDS_BYTES + cc * 16, src);
            }
            CP_COMMIT();
            CP_WAIT(1);
        } else {
            CP_WAIT(0);
        }
        __syncthreads();

        const uint32_t b_base = sbase + ((t & 1) ? OFF_B1 : OFF_B0) + b_base_rel;

        float c[4][4][4];
        float colacc[8];
        #pragma unroll
        for (int i = 0; i < 8; ++i) colacc[i] = 0.0f;

        // ---- pass 0: MMA for ni = 0..1 (b half 0) ----
        #pragma unroll
        for (int mi = 0; mi < 4; ++mi)
            #pragma unroll
            for (int ni = 0; ni < 2; ++ni)
                #pragma unroll
                for (int q = 0; q < 4; ++q) c[mi][ni][q] = 0.0f;
        #pragma unroll
        for (int ks = 0; ks < 8; ++ks) {
            uint32_t b0[4];
            LDM_X4(b0[0], b0[1], b0[2], b0[3], b_base + (uint32_t)(ks * 32));
            #pragma unroll
            for (int mi = 0; mi < 4; ++mi)
                #pragma unroll
                for (int ni = 0; ni < 2; ++ni)
                    MMA_BF16(c[mi][ni][0], c[mi][ni][1], c[mi][ni][2], c[mi][ni][3],
                             afr[ks][mi][0], afr[ks][mi][1], afr[ks][mi][2], afr[ks][mi][3],
                             b0[ni], b0[ni + 2]);
        }

        // ---- pass 1: MMA for ni = 2..3 with half0 epilogue interleaved ----
        #pragma unroll
        for (int mi = 0; mi < 4; ++mi)
            #pragma unroll
            for (int ni = 2; ni < 4; ++ni)
                #pragma unroll
                for (int q = 0; q < 4; ++q) c[mi][ni][q] = 0.0f;
        #pragma unroll
        for (int ks = 0; ks < 8; ++ks) {
            uint32_t b1[4];
            LDM_X4(b1[0], b1[1], b1[2], b1[3],
                   b_base + (uint32_t)(16 * LDS_BYTES + ks * 32));
            #pragma unroll
            for (int mi = 0; mi < 4; ++mi)
                #pragma unroll
                for (int ni = 0; ni < 2; ++ni)
                    MMA_BF16(c[mi][ni + 2][0], c[mi][ni + 2][1], c[mi][ni + 2][2], c[mi][ni + 2][3],
                             afr[ks][mi][0], afr[ks][mi][1], afr[ks][mi][2], afr[ks][mi][3],
                             b1[ni], b1[ni + 2]);
            // 4 half0 epilogue elements per ks iteration (32 total)
            EPI_ELEM(0, ks * 4 + 0);
            EPI_ELEM(0, ks * 4 + 1);
            EPI_ELEM(0, ks * 4 + 2);
            EPI_ELEM(0, ks * 4 + 3);
        }

        // ---- half1 epilogue tail ----
        #pragma unroll
        for (int e = 0; e < 32; ++e) EPI_ELEM(1, e);

        // flush colsums unless diagonal tile
        if (j != r) {
            #pragma unroll
            for (int i = 0; i < 8; ++i) {
                colacc[i] += __shfl_xor_sync(0xFFFFFFFFu, colacc[i], 4);
                colacc[i] += __shfl_xor_sync(0xFFFFFFFFu, colacc[i], 8);
                colacc[i] += __shfl_xor_sync(0xFFFFFFFFu, colacc[i], 16);
            }
            if (lane < 4) {
                int cb = j * 128 + wn * 32 + 2 * lane;
                #pragma unroll
                for (int ni = 0; ni < 4; ++ni) {
                    atomicAdd(&g_denom[cb + ni * 8 + 0], colacc[ni * 2 + 0]);
                    atomicAdd(&g_denom[cb + ni * 8 + 1], colacc[ni * 2 + 1]);
                }
            }
        }

        __syncthreads();

        if (t + 1 < cnt && rn != r) {
            #pragma unroll
            for (int i = 0; i < 8; ++i) {
                rowacc[i] += __shfl_xor_sync(0xFFFFFFFFu, rowacc[i], 1);
                rowacc[i] += __shfl_xor_sync(0xFFFFFFFFu, rowacc[i], 2);
            }
            if ((lane & 3) == 0) {
                int rb = r * 128 + wm * 64 + groupid;
                #pragma unroll
                for (int mi = 0; mi < 4; ++mi) {
                    atomicAdd(&g_denom[rb + mi * 16 + 0], rowacc[mi * 2 + 0]);
                    atomicAdd(&g_denom[rb + mi * 16 + 8], rowacc[mi * 2 + 1]);
                }
            }
            #pragma unroll
            for (int i = 0; i < 8; ++i) rowacc[i] = 0.0f;

            #pragma unroll
            for (int it = 0; it < 4; ++it) {
                int idx = it * NTHREADS + tid;
                int rr = idx >> 3, cc = idx & 7;
                uint4 v = *(const uint4*)(g_Zbf16 + (rn * 128 + rr) * D + cc * 8);
                *(uint4*)(smem + OFF_A + rr * LDS_BYTES + cc * 16) = v;
            }
            __syncthreads();
            #pragma unroll
            for (int ks = 0; ks < 8; ++ks)
                #pragma unroll
                for (int mi = 0; mi < 4; ++mi)
                    LDM_X4(afr[ks][mi][0], afr[ks][mi][1], afr[ks][mi][2], afr[ks][mi][3],
                           a_base + (uint32_t)(mi * 16 * LDS_BYTES + ks * 32));
        }

        r = rn; j = jn;
    }

    // final rowsum flush (strip of last processed tile)
    #pragma unroll
    for (int i = 0; i < 8; ++i) {
        rowacc[i] += __shfl_xor_sync(0xFFFFFFFFu, rowacc[i], 1);
        rowacc[i] += __shfl_xor_sync(0xFFFFFFFFu, rowacc[i], 2);
    }
    if ((lane & 3) == 0) {
        int lastidx = start + cnt - 1;
        int rr2;
        {
            float fr = (129.0f - sqrtf(129.0f * 129.0f - 8.0f * (float)lastidx)) * 0.5f;
            rr2 = (int)fr;
            if (rr2 < 0) rr2 = 0;
            if (rr2 > 63) rr2 = 63;
            while (rr2 < 63 && (rr2 + 1) * (129 - (rr2 + 1)) / 2 <= lastidx) ++rr2;
            while (rr2 > 0 && rr2 * (129 - rr2) / 2 > lastidx) --rr2;
        }
        int rb = rr2 * 128 + wm * 64 + groupid;
        #pragma unroll
        for (int mi = 0; mi < 4; ++mi) {
            atomicAdd(&g_denom[rb + mi * 16 + 0], rowacc[mi * 2 + 0]);
            atomicAdd(&g_denom[rb + mi * 16 + 8], rowacc[mi * 2 + 1]);
        }
    }

    // ---- fused finalize: last CTA computes the loss ----
    __shared__ unsigned int s_islast;
    __threadfence();
    __syncthreads();
    if (tid == 0)
        s_islast = (atomicAdd(&g_done, 1u) == NCTAS - 1) ? 1u : 0u;
    __syncthreads();

    if (s_islast) {
        __shared__ float red[NTHREADS];
        float s = 0.0f;
        for (int rr = tid; rr < TWO_B; rr += NTHREADS) {
            float denom = __ldcg(&g_denom[rr]) - 7.3890560989306495f;
            float pos = g_pos[rr & (BSZ - 1)];
            s += __logf(denom) - 2.0f * pos;
        }
        red[tid] = s;
        __syncthreads();
        #pragma unroll
        for (int st = NTHREADS / 2; st > 0; st >>= 1) {
            if (tid < st) red[tid] += red[tid + st];
            __syncthreads();
        }
        if (tid == 0) {
            out[0] = red[0] / (float)TWO_B;
            g_done = 0;     // reset for next graph replay
        }
    }
}

// ---------------------------------------------------------------------------
extern "C" void kernel_launch(void* const* d_in, const int* in_sizes, int n_in,
                              void* d_out, int out_size) {
    const float* p1 = (const float*)d_in[0];
    const float* p2 = (const float*)d_in[1];
    float* out = (float*)d_out;
    (void)in_sizes; (void)n_in; (void)out_size;

    cudaFuncSetAttribute(simsum_tri_kernel,
                         cudaFuncAttributeMaxDynamicSharedMemorySize,
                         SMEM_TOTAL);

    normalize_kernel<<<BSZ / 8, 256>>>(p1, p2);
    simsum_tri_kernel<<<NCTAS, NTHREADS, SMEM_TOTAL>>>(out);
}